// round 5
// baseline (speedup 1.0000x reference)
#include <cuda_runtime.h>
#include <cstdint>

#define VFULL 42
#define VP 48

typedef unsigned long long u64;

// ---------------- shared-memory layout (floats) ----------------
static constexpr int SW    = 0;              // weight tiles (padded)
static constexpr int SA    = 8704;           // x -> g1 ; g2 low
static constexpr int SB    = SA + 3072;      // h0 ; g2 high
static constexpr int SH1   = SB + 3072;      // h1 ; stage-E scratch (64 x 17)
static constexpr int SADJ  = SH1 + 6144;
static constexpr int SACC  = SADJ + 4608;
static constexpr int SRED  = SACC + 256;
static constexpr int SMEM_FLOATS = SRED + 16; // 25872 floats = 103488 B

__device__ __align__(16) float d_adj[2 * VP * VP];

// ---------------- f32x2 helpers (Blackwell packed fp32 FMA) ----------------
__device__ __forceinline__ void ffma2(u64& d, u64 a, u64 b) {
    asm("fma.rn.f32x2 %0, %1, %2, %0;" : "+l"(d) : "l"(a), "l"(b));
}
__device__ __forceinline__ u64 pack2(float lo, float hi) {
    u64 r; asm("mov.b64 %0, {%1, %2};" : "=l"(r) : "f"(lo), "f"(hi)); return r;
}
__device__ __forceinline__ float2 unpack2(u64 v) {
    float2 f; asm("mov.b64 {%0, %1}, %2;" : "=f"(f.x), "=f"(f.y) : "l"(v)); return f;
}

// ---------------- adjacency init: softmax(base_adj + B_i) ----------------
__global__ void build_adj_kernel(const float* __restrict__ B1,
                                 const float* __restrict__ B2) {
    __shared__ float base[VFULL * VFULL];
    int tid = threadIdx.x;
    for (int i = tid; i < VFULL * VFULL; i += blockDim.x) base[i] = 0.f;
    __syncthreads();
    if (tid == 0) {
        const int ei[23] = {0,1,2,3,0,5,6,7,0,9,10,11,0,13,14,15,0,17,18,19,5,9,13};
        const int ej[23] = {1,2,3,4,5,6,7,8,9,10,11,12,13,14,15,16,17,18,19,20,9,13,17};
        for (int e = 0; e < 23; e++) {
            int i = ei[e], j = ej[e];
            base[i*VFULL + j] = 1.f;  base[j*VFULL + i] = 1.f;
            base[(21+i)*VFULL + (21+j)] = 1.f;  base[(21+j)*VFULL + (21+i)] = 1.f;
        }
        base[0*VFULL + 21] = 1.f;  base[21*VFULL + 0] = 1.f;
        for (int v = 0; v < VFULL; v++) base[v*VFULL + v] += 1.f;
    }
    __syncthreads();
    for (int t = tid; t < 2 * VP; t += blockDim.x) {
        int m = t / VP, r = t % VP;
        const float* B = (m == 0) ? B1 : B2;
        float* dst = d_adj + m * VP * VP + r * VP;
        if (r >= VFULL) {
            for (int u = 0; u < VP; u++) dst[u] = 0.f;
        } else {
            float rs = 0.f;
            for (int u = 0; u < VFULL; u++) rs += base[r*VFULL + u];
            float inv = 1.f / rs;
            float vals[VFULL];
            float mx = -1e30f;
            for (int u = 0; u < VFULL; u++) {
                float v = base[r*VFULL + u] * inv + B[r*VFULL + u];
                vals[u] = v;
                mx = fmaxf(mx, v);
            }
            float s = 0.f;
            for (int u = 0; u < VFULL; u++) { vals[u] = expf(vals[u] - mx); s += vals[u]; }
            float is = 1.f / s;
            for (int u = 0; u < VFULL; u++) dst[u] = vals[u] * is;
            for (int u = VFULL; u < VP; u++) dst[u] = 0.f;
        }
    }
}

// ---------------- fused per-sample kernel ----------------
__global__ __launch_bounds__(256, 2)
void agcn_fused_kernel(
    const float* __restrict__ x,
    const float* __restrict__ W0, const float* __restrict__ b0,
    const float* __restrict__ gm0, const float* __restrict__ bt0,
    const float* __restrict__ W1, const float* __restrict__ b1,
    const float* __restrict__ gm1, const float* __restrict__ bt1,
    const float* __restrict__ W2, const float* __restrict__ b2,
    const float* __restrict__ gm2, const float* __restrict__ bt2,
    const float* __restrict__ Wc, const float* __restrict__ bc,
    float* __restrict__ out)
{
    extern __shared__ float sm[];
    const int tid = threadIdx.x;
    const int tx = tid & 15;          // stages B/D: 16 column groups
    const int ty = tid >> 4;          // stages B/D: 16 row groups x 3 joints
    const int w    = tid >> 5;        // warp id
    const int lane = tid & 31;
    const int jg   = lane & 7;        // 8 joint-groups per warp
    const int cg   = lane >> 3;       // 4 channel-groups per warp
    const int j0   = (w & 1) * 24 + jg * 3;   // 3 joints per thread (48 total)
    const int n = blockIdx.x;
    const float RSQ = rsqrtf(1.0f + 1e-5f);

    // ---- cooperative loads: x (zero-padded to 48 rows), adj, W0 (padded rows) ----
    {
        const float4* xs = (const float4*)(x + (size_t)n * (VFULL * 64));
        float4* d = (float4*)(sm + SA);
        for (int i = tid; i < 768; i += 256)
            d[i] = (i < 672) ? xs[i] : make_float4(0.f, 0.f, 0.f, 0.f);
        const float4* a = (const float4*)d_adj;
        float4* da = (float4*)(sm + SADJ);
        for (int i = tid; i < 1152; i += 256) da[i] = a[i];
        const float4* wsrc = (const float4*)W0;
        float4* dw = (float4*)(sm + SW);
        for (int i = tid; i < 1024; i += 256) {
            int row = i >> 4, col = i & 15;
            dw[row * 17 + col] = wsrc[i];
        }
        sm[SACC + tid] = 0.f;
    }
    __syncthreads();

    // ---- Stage A: h0 = relu(bn(x @ W0^T + b0)) -> sB (48 x 64), K = 64 ----
    // warp tile: 24 joints x 16 channels
    {
        const int c0 = (w >> 1) * 16 + cg * 4;   // 4 channels per thread
        u64 acc2[3][4] = {};
        const ulonglong2* A4 = (const ulonglong2*)(sm + SA);
        const ulonglong2* W4 = (const ulonglong2*)(sm + SW);
        for (int k = 0; k < 16; k++) {
            ulonglong2 a0 = A4[(j0 + 0) * 16 + k];
            ulonglong2 a1 = A4[(j0 + 1) * 16 + k];
            ulonglong2 a2 = A4[(j0 + 2) * 16 + k];
            #pragma unroll
            for (int j = 0; j < 4; j++) {
                ulonglong2 wv = W4[(c0 + j) * 17 + k];
                ffma2(acc2[0][j], a0.x, wv.x); ffma2(acc2[0][j], a0.y, wv.y);
                ffma2(acc2[1][j], a1.x, wv.x); ffma2(acc2[1][j], a1.y, wv.y);
                ffma2(acc2[2][j], a2.x, wv.x); ffma2(acc2[2][j], a2.y, wv.y);
            }
        }
        #pragma unroll
        for (int i = 0; i < 3; i++) {
            int v = j0 + i;
            float s  = (v < VFULL) ? __ldg(gm0 + v) * RSQ : 0.f;
            float be = (v < VFULL) ? __ldg(bt0 + v) : 0.f;
            float4 o;
            float* op = (float*)&o;
            #pragma unroll
            for (int j = 0; j < 4; j++) {
                float2 t = unpack2(acc2[i][j]);
                float val = fmaf(s, (t.x + t.y) + __ldg(b0 + c0 + j), be);
                op[j] = fmaxf(val, 0.f);
            }
            *(float4*)(sm + SB + v * 64 + c0) = o;
        }
    }
    __syncthreads();

    // ---- load W1 into padded sW; Stage B runs in parallel ----
    {
        const float4* wsrc = (const float4*)W1;
        float4* dw = (float4*)(sm + SW);
        for (int i = tid; i < 2048; i += 256) {
            int row = i >> 4, col = i & 15;
            dw[row * 17 + col] = wsrc[i];
        }
    }
    // ---- Stage B: g1 = adj1 @ h0 -> sA (48 x 64), K = 48 (channel-packed) ----
    {
        const int v0 = ty * 3;
        u64 acc2[3][2] = {};
        const float* adj = sm + SADJ;
        const ulonglong2* H4 = (const ulonglong2*)(sm + SB);
        for (int u4 = 0; u4 < 12; u4++) {
            float p0[4], p1[4], p2[4];
            *(float4*)p0 = *(const float4*)(adj + (v0 + 0) * VP + u4 * 4);
            *(float4*)p1 = *(const float4*)(adj + (v0 + 1) * VP + u4 * 4);
            *(float4*)p2 = *(const float4*)(adj + (v0 + 2) * VP + u4 * 4);
            #pragma unroll
            for (int k = 0; k < 4; k++) {
                ulonglong2 h = H4[(u4 * 4 + k) * 16 + tx];
                u64 a0p = pack2(p0[k], p0[k]);
                u64 a1p = pack2(p1[k], p1[k]);
                u64 a2p = pack2(p2[k], p2[k]);
                ffma2(acc2[0][0], a0p, h.x); ffma2(acc2[0][1], a0p, h.y);
                ffma2(acc2[1][0], a1p, h.x); ffma2(acc2[1][1], a1p, h.y);
                ffma2(acc2[2][0], a2p, h.x); ffma2(acc2[2][1], a2p, h.y);
            }
        }
        #pragma unroll
        for (int i = 0; i < 3; i++) {
            *(u64*)(sm + SA + (v0 + i) * 64 + tx * 4)     = acc2[i][0];
            *(u64*)(sm + SA + (v0 + i) * 64 + tx * 4 + 2) = acc2[i][1];
        }
    }
    __syncthreads();

    // ---- Stage C: h1 = relu(bn(g1 @ W1^T + b1)) -> sH1 (48 x 128), K = 64 ----
    // warp tile: 24 joints x 32 channels
    {
        const int c0 = (w >> 1) * 32 + cg * 8;   // 8 channels per thread
        u64 acc2[3][8] = {};
        const ulonglong2* A4 = (const ulonglong2*)(sm + SA);
        const ulonglong2* W4 = (const ulonglong2*)(sm + SW);
        for (int k = 0; k < 16; k++) {
            ulonglong2 a0 = A4[(j0 + 0) * 16 + k];
            ulonglong2 a1 = A4[(j0 + 1) * 16 + k];
            ulonglong2 a2 = A4[(j0 + 2) * 16 + k];
            #pragma unroll
            for (int j = 0; j < 8; j++) {
                ulonglong2 wv = W4[(c0 + j) * 17 + k];
                ffma2(acc2[0][j], a0.x, wv.x); ffma2(acc2[0][j], a0.y, wv.y);
                ffma2(acc2[1][j], a1.x, wv.x); ffma2(acc2[1][j], a1.y, wv.y);
                ffma2(acc2[2][j], a2.x, wv.x); ffma2(acc2[2][j], a2.y, wv.y);
            }
        }
        #pragma unroll
        for (int i = 0; i < 3; i++) {
            int v = j0 + i;
            float s  = (v < VFULL) ? __ldg(gm1 + v) * RSQ : 0.f;
            float be = (v < VFULL) ? __ldg(bt1 + v) : 0.f;
            float o[8];
            #pragma unroll
            for (int j = 0; j < 8; j++) {
                float2 t = unpack2(acc2[i][j]);
                float val = fmaf(s, (t.x + t.y) + __ldg(b1 + c0 + j), be);
                o[j] = fmaxf(val, 0.f);
            }
            *(float4*)(sm + SH1 + v * 128 + c0)     = *(float4*)&o[0];
            *(float4*)(sm + SH1 + v * 128 + c0 + 4) = *(float4*)&o[4];
        }
    }
    __syncthreads();

    // ---- Stage D: g2 = adj2 @ h1 -> sA (48 x 128), K = 48 (channel-packed) ----
    // channel split: thread owns ch [tx*4, tx*4+4) and [64+tx*4, 64+tx*4+4)
    {
        const int v0 = ty * 3;
        u64 acc2[3][4] = {};
        const float* adj = sm + SADJ + VP * VP;
        const ulonglong2* H4 = (const ulonglong2*)(sm + SH1);
        for (int u4 = 0; u4 < 12; u4++) {
            float p0[4], p1[4], p2[4];
            *(float4*)p0 = *(const float4*)(adj + (v0 + 0) * VP + u4 * 4);
            *(float4*)p1 = *(const float4*)(adj + (v0 + 1) * VP + u4 * 4);
            *(float4*)p2 = *(const float4*)(adj + (v0 + 2) * VP + u4 * 4);
            #pragma unroll
            for (int k = 0; k < 4; k++) {
                int u = u4 * 4 + k;
                ulonglong2 ha = H4[u * 32 + tx];        // ch tx*4 .. +3
                ulonglong2 hb = H4[u * 32 + 16 + tx];   // ch 64+tx*4 .. +3
                u64 a0p = pack2(p0[k], p0[k]);
                u64 a1p = pack2(p1[k], p1[k]);
                u64 a2p = pack2(p2[k], p2[k]);
                ffma2(acc2[0][0], a0p, ha.x); ffma2(acc2[0][1], a0p, ha.y);
                ffma2(acc2[0][2], a0p, hb.x); ffma2(acc2[0][3], a0p, hb.y);
                ffma2(acc2[1][0], a1p, ha.x); ffma2(acc2[1][1], a1p, ha.y);
                ffma2(acc2[1][2], a1p, hb.x); ffma2(acc2[1][3], a1p, hb.y);
                ffma2(acc2[2][0], a2p, ha.x); ffma2(acc2[2][1], a2p, ha.y);
                ffma2(acc2[2][2], a2p, hb.x); ffma2(acc2[2][3], a2p, hb.y);
            }
        }
        #pragma unroll
        for (int i = 0; i < 3; i++) {
            float* row = sm + SA + (v0 + i) * 128;
            *(u64*)(row + tx * 4)          = acc2[i][0];
            *(u64*)(row + tx * 4 + 2)      = acc2[i][1];
            *(u64*)(row + 64 + tx * 4)     = acc2[i][2];
            *(u64*)(row + 64 + tx * 4 + 2) = acc2[i][3];
        }
    }
    __syncthreads();

    // ---- Stage E: 4 tiles of 64 out-channels of W2; relu(bn(.)) + joint-sum ----
    // warp tile: 24 joints x 16 channels; scratch stride 17 (conflict-free)
    const int c0e  = (w >> 1) * 16 + cg * 4;    // local channel base (0..60)
    const int slot = (w & 1) * 8 + jg;          // 16 partial-sum slots per channel
    for (int et = 0; et < 4; et++) {
        {   // load W2 tile (64 x 128) into padded sW
            const float4* wsrc = (const float4*)(W2 + et * 64 * 128);
            float4* dw = (float4*)(sm + SW);
            for (int i = tid; i < 2048; i += 256) {
                int row = i >> 5, col = i & 31;
                dw[row * 33 + col] = wsrc[i];
            }
        }
        __syncthreads();
        float part[4] = {};
        {
            u64 acc2[3][4] = {};
            const ulonglong2* G4 = (const ulonglong2*)(sm + SA);
            const ulonglong2* W4 = (const ulonglong2*)(sm + SW);
            for (int k = 0; k < 32; k++) {
                ulonglong2 a0 = G4[(j0 + 0) * 32 + k];
                ulonglong2 a1 = G4[(j0 + 1) * 32 + k];
                ulonglong2 a2 = G4[(j0 + 2) * 32 + k];
                #pragma unroll
                for (int j = 0; j < 4; j++) {
                    ulonglong2 wv = W4[(c0e + j) * 33 + k];
                    ffma2(acc2[0][j], a0.x, wv.x); ffma2(acc2[0][j], a0.y, wv.y);
                    ffma2(acc2[1][j], a1.x, wv.x); ffma2(acc2[1][j], a1.y, wv.y);
                    ffma2(acc2[2][j], a2.x, wv.x); ffma2(acc2[2][j], a2.y, wv.y);
                }
            }
            #pragma unroll
            for (int i = 0; i < 3; i++) {
                int v = j0 + i;
                if (v < VFULL) {
                    float s  = __ldg(gm2 + v) * RSQ;
                    float be = __ldg(bt2 + v);
                    #pragma unroll
                    for (int j = 0; j < 4; j++) {
                        int e = et * 64 + c0e + j;
                        float2 t = unpack2(acc2[i][j]);
                        float val = fmaf(s, (t.x + t.y) + __ldg(b2 + e), be);
                        part[j] += fmaxf(val, 0.f);
                    }
                }
            }
        }
        // deterministic reduce over the 16 slots (scratch in sH1, stride 17)
        #pragma unroll
        for (int j = 0; j < 4; j++)
            sm[SH1 + (c0e + j) * 17 + slot] = part[j];
        __syncthreads();
        if (tid < 64) {
            float s = 0.f;
            #pragma unroll
            for (int t = 0; t < 16; t++) s += sm[SH1 + tid * 17 + t];
            sm[SACC + et * 64 + tid] += s;
        }
        __syncthreads();
    }

    // ---- classifier: out = (sum_v h2 / 42) @ Wc^T + bc ----
    {
        float f = sm[SACC + tid] * (1.0f / 42.0f);
        float p0 = f * __ldg(Wc + tid);
        float p1 = f * __ldg(Wc + 256 + tid);
        #pragma unroll
        for (int o = 16; o > 0; o >>= 1) {
            p0 += __shfl_xor_sync(0xffffffffu, p0, o);
            p1 += __shfl_xor_sync(0xffffffffu, p1, o);
        }
        if ((tid & 31) == 0) { sm[SRED + w] = p0; sm[SRED + 8 + w] = p1; }
        __syncthreads();
        if (tid == 0) {
            float s0 = 0.f, s1 = 0.f;
            for (int q = 0; q < 8; q++) { s0 += sm[SRED + q]; s1 += sm[SRED + 8 + q]; }
            out[(size_t)n * 2 + 0] = s0 + __ldg(bc + 0);
            out[(size_t)n * 2 + 1] = s1 + __ldg(bc + 1);
        }
    }
}

extern "C" void kernel_launch(void* const* d_in, const int* in_sizes, int n_in,
                              void* d_out, int out_size) {
    const float* x   = (const float*)d_in[0];
    const float* W0  = (const float*)d_in[1];
    const float* b0  = (const float*)d_in[2];
    const float* gm0 = (const float*)d_in[3];
    const float* bt0 = (const float*)d_in[4];
    const float* W1  = (const float*)d_in[5];
    const float* b1  = (const float*)d_in[6];
    const float* B1  = (const float*)d_in[7];
    const float* gm1 = (const float*)d_in[8];
    const float* bt1 = (const float*)d_in[9];
    const float* W2  = (const float*)d_in[10];
    const float* b2  = (const float*)d_in[11];
    const float* B2  = (const float*)d_in[12];
    const float* gm2 = (const float*)d_in[13];
    const float* bt2 = (const float*)d_in[14];
    const float* Wc  = (const float*)d_in[15];
    const float* bc  = (const float*)d_in[16];
    float* out = (float*)d_out;

    int N = in_sizes[0] / (VFULL * 64);

    build_adj_kernel<<<1, 128>>>(B1, B2);

    size_t smem = (size_t)SMEM_FLOATS * sizeof(float);
    cudaFuncSetAttribute(agcn_fused_kernel,
                         cudaFuncAttributeMaxDynamicSharedMemorySize, (int)smem);
    agcn_fused_kernel<<<N, 256, smem>>>(x, W0, b0, gm0, bt0,
                                        W1, b1, gm1, bt1,
                                        W2, b2, gm2, bt2,
                                        Wc, bc, out);
}

// round 6
// speedup vs baseline: 3.5694x; 3.5694x over previous
#include <cuda_runtime.h>
#include <cstdint>

#define VFULL 42
#define VP 48

typedef unsigned long long u64;

// ---------------- shared-memory layout (floats) ----------------
// Activation rows padded: 64-ch buffers stride 68 floats (272B, order-8 mod 128B),
// 128-ch buffers stride 140 floats (560B, order-8 mod 128B) -> conflict-free
// strided row access across the 8 joint-groups of a warp.
static constexpr int SW    = 0;               // weight tiles (padded): 2176 f4
static constexpr int SA    = 8704;            // x -> g1 (48x68) ; g2 (48x140) spans SA..SB
static constexpr int SB    = SA + 3360;       // h0 (48x68)
static constexpr int SH1   = SB + 3360;       // h1 (48x140) ; stage-E scratch
static constexpr int SADJ  = SH1 + 6720;
static constexpr int SACC  = SADJ + 4608;
static constexpr int SRED  = SACC + 256;
static constexpr int SMEM_FLOATS = SRED + 16; // 27024 floats = 108096 B

__device__ __align__(16) float d_adj[2 * VP * VP];

// ---------------- f32x2 helpers (Blackwell packed fp32 FMA) ----------------
__device__ __forceinline__ void ffma2(u64& d, u64 a, u64 b) {
    asm("fma.rn.f32x2 %0, %1, %2, %0;" : "+l"(d) : "l"(a), "l"(b));
}
__device__ __forceinline__ u64 pack2(float lo, float hi) {
    u64 r; asm("mov.b64 %0, {%1, %2};" : "=l"(r) : "f"(lo), "f"(hi)); return r;
}
__device__ __forceinline__ float2 unpack2(u64 v) {
    float2 f; asm("mov.b64 {%0, %1}, %2;" : "=f"(f.x), "=f"(f.y) : "l"(v)); return f;
}

// ---------------- adjacency init: softmax(base_adj + B_i) ----------------
__global__ void build_adj_kernel(const float* __restrict__ B1,
                                 const float* __restrict__ B2) {
    __shared__ float base[VFULL * VFULL];
    int tid = threadIdx.x;
    for (int i = tid; i < VFULL * VFULL; i += blockDim.x) base[i] = 0.f;
    __syncthreads();
    if (tid == 0) {
        const int ei[23] = {0,1,2,3,0,5,6,7,0,9,10,11,0,13,14,15,0,17,18,19,5,9,13};
        const int ej[23] = {1,2,3,4,5,6,7,8,9,10,11,12,13,14,15,16,17,18,19,20,9,13,17};
        for (int e = 0; e < 23; e++) {
            int i = ei[e], j = ej[e];
            base[i*VFULL + j] = 1.f;  base[j*VFULL + i] = 1.f;
            base[(21+i)*VFULL + (21+j)] = 1.f;  base[(21+j)*VFULL + (21+i)] = 1.f;
        }
        base[0*VFULL + 21] = 1.f;  base[21*VFULL + 0] = 1.f;
        for (int v = 0; v < VFULL; v++) base[v*VFULL + v] += 1.f;
    }
    __syncthreads();
    for (int t = tid; t < 2 * VP; t += blockDim.x) {
        int m = t / VP, r = t % VP;
        const float* B = (m == 0) ? B1 : B2;
        float* dst = d_adj + m * VP * VP + r * VP;
        if (r >= VFULL) {
            for (int u = 0; u < VP; u++) dst[u] = 0.f;
        } else {
            float rs = 0.f;
            for (int u = 0; u < VFULL; u++) rs += base[r*VFULL + u];
            float inv = 1.f / rs;
            float vals[VFULL];
            float mx = -1e30f;
            for (int u = 0; u < VFULL; u++) {
                float v = base[r*VFULL + u] * inv + B[r*VFULL + u];
                vals[u] = v;
                mx = fmaxf(mx, v);
            }
            float s = 0.f;
            for (int u = 0; u < VFULL; u++) { vals[u] = expf(vals[u] - mx); s += vals[u]; }
            float is = 1.f / s;
            for (int u = 0; u < VFULL; u++) dst[u] = vals[u] * is;
            for (int u = VFULL; u < VP; u++) dst[u] = 0.f;
        }
    }
}

// ---------------- fused per-sample kernel ----------------
__global__ __launch_bounds__(256, 2)
void agcn_fused_kernel(
    const float* __restrict__ x,
    const float* __restrict__ W0, const float* __restrict__ b0,
    const float* __restrict__ gm0, const float* __restrict__ bt0,
    const float* __restrict__ W1, const float* __restrict__ b1,
    const float* __restrict__ gm1, const float* __restrict__ bt1,
    const float* __restrict__ W2, const float* __restrict__ b2,
    const float* __restrict__ gm2, const float* __restrict__ bt2,
    const float* __restrict__ Wc, const float* __restrict__ bc,
    float* __restrict__ out)
{
    extern __shared__ float sm[];
    const int tid = threadIdx.x;
    const int tx = tid & 15;          // stages B/D: 16 column groups
    const int ty = tid >> 4;          // stages B/D: 16 row groups x 3 joints
    const int w    = tid >> 5;        // warp id
    const int lane = tid & 31;
    const int jg   = lane & 7;        // 8 joint-groups per warp
    const int cg   = lane >> 3;       // 4 channel-groups per warp
    const int j0   = (w & 1) * 24 + jg * 3;   // 3 joints per thread (48 total)
    const int n = blockIdx.x;
    const float RSQ = rsqrtf(1.0f + 1e-5f);

    // ---- cooperative loads: x (zero-padded, stride 17 f4), adj, W0 (17 f4) ----
    {
        const float4* xs = (const float4*)(x + (size_t)n * (VFULL * 64));
        float4* d = (float4*)(sm + SA);
        for (int i = tid; i < 768; i += 256) {
            int row = i >> 4, col = i & 15;
            d[row * 17 + col] = (i < 672) ? xs[i] : make_float4(0.f, 0.f, 0.f, 0.f);
        }
        const float4* a = (const float4*)d_adj;
        float4* da = (float4*)(sm + SADJ);
        for (int i = tid; i < 1152; i += 256) da[i] = a[i];
        const float4* wsrc = (const float4*)W0;
        float4* dw = (float4*)(sm + SW);
        for (int i = tid; i < 1024; i += 256) {
            int row = i >> 4, col = i & 15;
            dw[row * 17 + col] = wsrc[i];
        }
        sm[SACC + tid] = 0.f;
    }
    __syncthreads();

    // ---- Stage A: h0 = relu(bn(x @ W0^T + b0)) -> sB (48 x 64, stride 68) ----
    // warp tile 24 joints x 16 channels; thread channels c = cb + 4j (strided)
    {
        const int cb = (w >> 1) * 16 + cg;
        u64 acc2[3][4] = {};
        const ulonglong2* A4 = (const ulonglong2*)(sm + SA);
        const ulonglong2* W4 = (const ulonglong2*)(sm + SW);
        for (int k = 0; k < 16; k++) {
            ulonglong2 a0 = A4[(j0 + 0) * 17 + k];
            ulonglong2 a1 = A4[(j0 + 1) * 17 + k];
            ulonglong2 a2 = A4[(j0 + 2) * 17 + k];
            #pragma unroll
            for (int j = 0; j < 4; j++) {
                ulonglong2 wv = W4[(cb + 4 * j) * 17 + k];
                ffma2(acc2[0][j], a0.x, wv.x); ffma2(acc2[0][j], a0.y, wv.y);
                ffma2(acc2[1][j], a1.x, wv.x); ffma2(acc2[1][j], a1.y, wv.y);
                ffma2(acc2[2][j], a2.x, wv.x); ffma2(acc2[2][j], a2.y, wv.y);
            }
        }
        #pragma unroll
        for (int i = 0; i < 3; i++) {
            int v = j0 + i;
            float s  = (v < VFULL) ? __ldg(gm0 + v) * RSQ : 0.f;
            float be = (v < VFULL) ? __ldg(bt0 + v) : 0.f;
            #pragma unroll
            for (int j = 0; j < 4; j++) {
                int c = cb + 4 * j;
                float2 t = unpack2(acc2[i][j]);
                float val = fmaf(s, (t.x + t.y) + __ldg(b0 + c), be);
                sm[SB + v * 68 + c] = fmaxf(val, 0.f);
            }
        }
    }
    __syncthreads();

    // ---- load W1 into padded sW; Stage B runs in parallel ----
    {
        const float4* wsrc = (const float4*)W1;
        float4* dw = (float4*)(sm + SW);
        for (int i = tid; i < 2048; i += 256) {
            int row = i >> 4, col = i & 15;
            dw[row * 17 + col] = wsrc[i];
        }
    }
    // ---- Stage B: g1 = adj1 @ h0 -> sA (48 x 64, stride 68), K = 48 ----
    {
        const int v0 = ty * 3;
        u64 acc2[3][2] = {};
        const float* adj = sm + SADJ;
        const ulonglong2* H4 = (const ulonglong2*)(sm + SB);
        for (int u4 = 0; u4 < 12; u4++) {
            float p0[4], p1[4], p2[4];
            *(float4*)p0 = *(const float4*)(adj + (v0 + 0) * VP + u4 * 4);
            *(float4*)p1 = *(const float4*)(adj + (v0 + 1) * VP + u4 * 4);
            *(float4*)p2 = *(const float4*)(adj + (v0 + 2) * VP + u4 * 4);
            #pragma unroll
            for (int k = 0; k < 4; k++) {
                ulonglong2 h = H4[(u4 * 4 + k) * 17 + tx];
                u64 a0p = pack2(p0[k], p0[k]);
                u64 a1p = pack2(p1[k], p1[k]);
                u64 a2p = pack2(p2[k], p2[k]);
                ffma2(acc2[0][0], a0p, h.x); ffma2(acc2[0][1], a0p, h.y);
                ffma2(acc2[1][0], a1p, h.x); ffma2(acc2[1][1], a1p, h.y);
                ffma2(acc2[2][0], a2p, h.x); ffma2(acc2[2][1], a2p, h.y);
            }
        }
        #pragma unroll
        for (int i = 0; i < 3; i++) {
            *(u64*)(sm + SA + (v0 + i) * 68 + tx * 4)     = acc2[i][0];
            *(u64*)(sm + SA + (v0 + i) * 68 + tx * 4 + 2) = acc2[i][1];
        }
    }
    __syncthreads();

    // ---- Stage C: h1 = relu(bn(g1 @ W1^T + b1)) -> sH1 (48 x 128, stride 140) ----
    // warp tile 24 joints x 32 channels; thread channels c = cb + 4j
    {
        const int cb = (w >> 1) * 32 + cg;
        u64 acc2[3][8] = {};
        const ulonglong2* A4 = (const ulonglong2*)(sm + SA);
        const ulonglong2* W4 = (const ulonglong2*)(sm + SW);
        for (int k = 0; k < 16; k++) {
            ulonglong2 a0 = A4[(j0 + 0) * 17 + k];
            ulonglong2 a1 = A4[(j0 + 1) * 17 + k];
            ulonglong2 a2 = A4[(j0 + 2) * 17 + k];
            #pragma unroll
            for (int j = 0; j < 8; j++) {
                ulonglong2 wv = W4[(cb + 4 * j) * 17 + k];
                ffma2(acc2[0][j], a0.x, wv.x); ffma2(acc2[0][j], a0.y, wv.y);
                ffma2(acc2[1][j], a1.x, wv.x); ffma2(acc2[1][j], a1.y, wv.y);
                ffma2(acc2[2][j], a2.x, wv.x); ffma2(acc2[2][j], a2.y, wv.y);
            }
        }
        #pragma unroll
        for (int i = 0; i < 3; i++) {
            int v = j0 + i;
            float s  = (v < VFULL) ? __ldg(gm1 + v) * RSQ : 0.f;
            float be = (v < VFULL) ? __ldg(bt1 + v) : 0.f;
            #pragma unroll
            for (int j = 0; j < 8; j++) {
                int c = cb + 4 * j;
                float2 t = unpack2(acc2[i][j]);
                float val = fmaf(s, (t.x + t.y) + __ldg(b1 + c), be);
                sm[SH1 + v * 140 + c] = fmaxf(val, 0.f);
            }
        }
    }
    __syncthreads();

    // ---- Stage D: g2 = adj2 @ h1 -> sA (48 x 128, stride 140), K = 48 ----
    {
        const int v0 = ty * 3;
        u64 acc2[3][4] = {};
        const float* adj = sm + SADJ + VP * VP;
        const ulonglong2* H4 = (const ulonglong2*)(sm + SH1);
        for (int u4 = 0; u4 < 12; u4++) {
            float p0[4], p1[4], p2[4];
            *(float4*)p0 = *(const float4*)(adj + (v0 + 0) * VP + u4 * 4);
            *(float4*)p1 = *(const float4*)(adj + (v0 + 1) * VP + u4 * 4);
            *(float4*)p2 = *(const float4*)(adj + (v0 + 2) * VP + u4 * 4);
            #pragma unroll
            for (int k = 0; k < 4; k++) {
                int u = u4 * 4 + k;
                ulonglong2 ha = H4[u * 35 + tx];        // ch tx*4 .. +3
                ulonglong2 hb = H4[u * 35 + 16 + tx];   // ch 64+tx*4 .. +3
                u64 a0p = pack2(p0[k], p0[k]);
                u64 a1p = pack2(p1[k], p1[k]);
                u64 a2p = pack2(p2[k], p2[k]);
                ffma2(acc2[0][0], a0p, ha.x); ffma2(acc2[0][1], a0p, ha.y);
                ffma2(acc2[0][2], a0p, hb.x); ffma2(acc2[0][3], a0p, hb.y);
                ffma2(acc2[1][0], a1p, ha.x); ffma2(acc2[1][1], a1p, ha.y);
                ffma2(acc2[1][2], a1p, hb.x); ffma2(acc2[1][3], a1p, hb.y);
                ffma2(acc2[2][0], a2p, ha.x); ffma2(acc2[2][1], a2p, ha.y);
                ffma2(acc2[2][2], a2p, hb.x); ffma2(acc2[2][3], a2p, hb.y);
            }
        }
        #pragma unroll
        for (int i = 0; i < 3; i++) {
            float* row = sm + SA + (v0 + i) * 140;
            *(u64*)(row + tx * 4)          = acc2[i][0];
            *(u64*)(row + tx * 4 + 2)      = acc2[i][1];
            *(u64*)(row + 64 + tx * 4)     = acc2[i][2];
            *(u64*)(row + 64 + tx * 4 + 2) = acc2[i][3];
        }
    }
    __syncthreads();

    // ---- Stage E: 4 tiles of 64 out-channels of W2; relu(bn(.)) + joint-sum ----
    // warp tile 24 joints x 16 channels; scratch stride 17 in sH1
    const int cbE  = (w >> 1) * 16 + cg;        // local channels cbE + 4j
    const int slot = (w & 1) * 8 + jg;          // 16 partial-sum slots per channel
    for (int et = 0; et < 4; et++) {
        {   // load W2 tile (64 x 128) into padded sW (33 f4 stride)
            const float4* wsrc = (const float4*)(W2 + et * 64 * 128);
            float4* dw = (float4*)(sm + SW);
            for (int i = tid; i < 2048; i += 256) {
                int row = i >> 5, col = i & 31;
                dw[row * 33 + col] = wsrc[i];
            }
        }
        __syncthreads();
        float part[4] = {};
        {
            u64 acc2[3][4] = {};
            const ulonglong2* G4 = (const ulonglong2*)(sm + SA);
            const ulonglong2* W4 = (const ulonglong2*)(sm + SW);
            for (int k = 0; k < 32; k++) {
                ulonglong2 a0 = G4[(j0 + 0) * 35 + k];
                ulonglong2 a1 = G4[(j0 + 1) * 35 + k];
                ulonglong2 a2 = G4[(j0 + 2) * 35 + k];
                #pragma unroll
                for (int j = 0; j < 4; j++) {
                    ulonglong2 wv = W4[(cbE + 4 * j) * 33 + k];
                    ffma2(acc2[0][j], a0.x, wv.x); ffma2(acc2[0][j], a0.y, wv.y);
                    ffma2(acc2[1][j], a1.x, wv.x); ffma2(acc2[1][j], a1.y, wv.y);
                    ffma2(acc2[2][j], a2.x, wv.x); ffma2(acc2[2][j], a2.y, wv.y);
                }
            }
            #pragma unroll
            for (int i = 0; i < 3; i++) {
                int v = j0 + i;
                if (v < VFULL) {
                    float s  = __ldg(gm2 + v) * RSQ;
                    float be = __ldg(bt2 + v);
                    #pragma unroll
                    for (int j = 0; j < 4; j++) {
                        int e = et * 64 + cbE + 4 * j;
                        float2 t = unpack2(acc2[i][j]);
                        float val = fmaf(s, (t.x + t.y) + __ldg(b2 + e), be);
                        part[j] += fmaxf(val, 0.f);
                    }
                }
            }
        }
        // deterministic reduce over the 16 slots (scratch in sH1, stride 17)
        #pragma unroll
        for (int j = 0; j < 4; j++)
            sm[SH1 + (cbE + 4 * j) * 17 + slot] = part[j];
        __syncthreads();
        if (tid < 64) {
            float s = 0.f;
            #pragma unroll
            for (int t = 0; t < 16; t++) s += sm[SH1 + tid * 17 + t];
            sm[SACC + et * 64 + tid] += s;
        }
        __syncthreads();
    }

    // ---- classifier: out = (sum_v h2 / 42) @ Wc^T + bc ----
    {
        float f = sm[SACC + tid] * (1.0f / 42.0f);
        float p0 = f * __ldg(Wc + tid);
        float p1 = f * __ldg(Wc + 256 + tid);
        #pragma unroll
        for (int o = 16; o > 0; o >>= 1) {
            p0 += __shfl_xor_sync(0xffffffffu, p0, o);
            p1 += __shfl_xor_sync(0xffffffffu, p1, o);
        }
        if ((tid & 31) == 0) { sm[SRED + w] = p0; sm[SRED + 8 + w] = p1; }
        __syncthreads();
        if (tid == 0) {
            float s0 = 0.f, s1 = 0.f;
            for (int q = 0; q < 8; q++) { s0 += sm[SRED + q]; s1 += sm[SRED + 8 + q]; }
            out[(size_t)n * 2 + 0] = s0 + __ldg(bc + 0);
            out[(size_t)n * 2 + 1] = s1 + __ldg(bc + 1);
        }
    }
}

extern "C" void kernel_launch(void* const* d_in, const int* in_sizes, int n_in,
                              void* d_out, int out_size) {
    const float* x   = (const float*)d_in[0];
    const float* W0  = (const float*)d_in[1];
    const float* b0  = (const float*)d_in[2];
    const float* gm0 = (const float*)d_in[3];
    const float* bt0 = (const float*)d_in[4];
    const float* W1  = (const float*)d_in[5];
    const float* b1  = (const float*)d_in[6];
    const float* B1  = (const float*)d_in[7];
    const float* gm1 = (const float*)d_in[8];
    const float* bt1 = (const float*)d_in[9];
    const float* W2  = (const float*)d_in[10];
    const float* b2  = (const float*)d_in[11];
    const float* B2  = (const float*)d_in[12];
    const float* gm2 = (const float*)d_in[13];
    const float* bt2 = (const float*)d_in[14];
    const float* Wc  = (const float*)d_in[15];
    const float* bc  = (const float*)d_in[16];
    float* out = (float*)d_out;

    int N = in_sizes[0] / (VFULL * 64);

    build_adj_kernel<<<1, 128>>>(B1, B2);

    size_t smem = (size_t)SMEM_FLOATS * sizeof(float);
    cudaFuncSetAttribute(agcn_fused_kernel,
                         cudaFuncAttributeMaxDynamicSharedMemorySize, (int)smem);
    agcn_fused_kernel<<<N, 256, smem>>>(x, W0, b0, gm0, bt0,
                                        W1, b1, gm1, bt1,
                                        W2, b2, gm2, bt2,
                                        Wc, bc, out);
}